// round 6
// baseline (speedup 1.0000x reference)
#include <cuda_runtime.h>
#include <math.h>

// Problem dims
#define BB 2
#define SS 2048
#define DD 1024
#define HH 16
#define HD 64
#define ROWS (BB*SS)          // 4096
#define EPS 1e-6f

// ---------------- scratch (device globals; no allocation allowed) ----------
__device__ float g_xn  [ROWS * DD];          // layernorm output
__device__ float g_qkv [ROWS * 3 * DD];      // qkv projection
__device__ float g_q   [BB * HH * SS * HD];  // [b,h,s,d]
__device__ float g_k   [BB * HH * SS * HD];
__device__ float g_v   [BB * HH * SS * HD];
__device__ float g_attn[ROWS * DD];          // attention out, [b,s,h*64+d]

// ---------------- kernel 1: row LayerNorm over D=1024 ---------------------
__global__ __launch_bounds__(256) void ln_kernel(
    const float* __restrict__ x, const float* __restrict__ scale,
    const float* __restrict__ bias, float* __restrict__ y)
{
    __shared__ float sh[8];
    const int t = threadIdx.x;
    const size_t row = blockIdx.x;
    const float* xr = x + row * DD;

    float v0 = xr[t], v1 = xr[t + 256], v2 = xr[t + 512], v3 = xr[t + 768];

    float s = v0 + v1 + v2 + v3;
    #pragma unroll
    for (int o = 16; o; o >>= 1) s += __shfl_xor_sync(0xffffffffu, s, o);
    if ((t & 31) == 0) sh[t >> 5] = s;
    __syncthreads();
    float tot = 0.f;
    #pragma unroll
    for (int i = 0; i < 8; i++) tot += sh[i];
    const float mean = tot * (1.f / 1024.f);

    float a0 = v0 - mean, a1 = v1 - mean, a2 = v2 - mean, a3 = v3 - mean;
    float sq = a0*a0 + a1*a1 + a2*a2 + a3*a3;
    #pragma unroll
    for (int o = 16; o; o >>= 1) sq += __shfl_xor_sync(0xffffffffu, sq, o);
    __syncthreads();
    if ((t & 31) == 0) sh[t >> 5] = sq;
    __syncthreads();
    float tsq = 0.f;
    #pragma unroll
    for (int i = 0; i < 8; i++) tsq += sh[i];
    const float rstd = rsqrtf(tsq * (1.f / 1024.f) + EPS);

    float* yr = y + row * DD;
    yr[t      ] = a0 * rstd * scale[t      ] + bias[t      ];
    yr[t + 256] = a1 * rstd * scale[t + 256] + bias[t + 256];
    yr[t + 512] = a2 * rstd * scale[t + 512] + bias[t + 512];
    yr[t + 768] = a3 * rstd * scale[t + 768] + bias[t + 768];
}

// ---------------- kernel 2: SGEMM 128x128x8, 8x8 per thread, + bias -------
__global__ __launch_bounds__(256) void sgemm_bias(
    const float* __restrict__ A, const float* __restrict__ B,
    const float* __restrict__ bias, float* __restrict__ C,
    int M, int N, int K)
{
    __shared__ float As[8][128];
    __shared__ float Bs[8][128];

    const int tid = threadIdx.x;
    const int tx = tid & 15;      // 0..15  -> N direction
    const int ty = tid >> 4;      // 0..15  -> M direction
    const int rowBase = blockIdx.y * 128;
    const int colBase = blockIdx.x * 128;

    const int aRow = tid >> 1;            // 0..127
    const int aCol = (tid & 1) * 4;       // 0 or 4
    const int bRow = tid >> 5;            // 0..7
    const int bCol = (tid & 31) * 4;      // 0..124

    float acc[8][8];
    #pragma unroll
    for (int i = 0; i < 8; i++)
        #pragma unroll
        for (int j = 0; j < 8; j++) acc[i][j] = 0.f;

    for (int k0 = 0; k0 < K; k0 += 8) {
        float4 a = *(const float4*)(A + (size_t)(rowBase + aRow) * K + k0 + aCol);
        As[aCol + 0][aRow] = a.x;
        As[aCol + 1][aRow] = a.y;
        As[aCol + 2][aRow] = a.z;
        As[aCol + 3][aRow] = a.w;
        float4 b = *(const float4*)(B + (size_t)(k0 + bRow) * N + colBase + bCol);
        *(float4*)&Bs[bRow][bCol] = b;
        __syncthreads();

        #pragma unroll
        for (int k = 0; k < 8; k++) {
            float ra[8], rb[8];
            #pragma unroll
            for (int i = 0; i < 8; i++) ra[i] = As[k][ty * 8 + i];
            #pragma unroll
            for (int j = 0; j < 8; j++) rb[j] = Bs[k][tx * 8 + j];
            #pragma unroll
            for (int i = 0; i < 8; i++)
                #pragma unroll
                for (int j = 0; j < 8; j++) acc[i][j] += ra[i] * rb[j];
        }
        __syncthreads();
    }

    #pragma unroll
    for (int i = 0; i < 8; i++) {
        const size_t row = rowBase + ty * 8 + i;
        #pragma unroll
        for (int j = 0; j < 8; j += 4) {
            const int col = colBase + tx * 8 + j;
            float4 o;
            o.x = acc[i][j + 0] + bias[col + 0];
            o.y = acc[i][j + 1] + bias[col + 1];
            o.z = acc[i][j + 2] + bias[col + 2];
            o.w = acc[i][j + 3] + bias[col + 3];
            *(float4*)(C + row * N + col) = o;
        }
    }
}

// ---------------- kernel 3: per-head LN (q,k) + RoPE + transpose ----------
// one warp per (b,s,h); lane handles elements d and d+32
__global__ __launch_bounds__(128) void qk_rope_kernel(
    const float* __restrict__ qkv,
    const float* __restrict__ q_scale, const float* __restrict__ k_scale,
    float* __restrict__ Q, float* __restrict__ K, float* __restrict__ V)
{
    const int w = blockIdx.x * 4 + (threadIdx.x >> 5);
    const int lane = threadIdx.x & 31;
    const int h = w % HH;
    const int s = (w / HH) % SS;
    const int b = w / (HH * SS);

    const float* row = qkv + (size_t)(b * SS + s) * (3 * DD) + h * HD;
    float q0 = row[lane],        q1 = row[lane + 32];
    float k0 = row[DD + lane],   k1 = row[DD + lane + 32];
    float v0 = row[2*DD + lane], v1 = row[2*DD + lane + 32];

    // ---- q LN ----
    float mu = q0 + q1;
    #pragma unroll
    for (int o = 16; o; o >>= 1) mu += __shfl_xor_sync(0xffffffffu, mu, o);
    mu *= (1.f / 64.f);
    float a0 = q0 - mu, a1 = q1 - mu;
    float var = a0 * a0 + a1 * a1;
    #pragma unroll
    for (int o = 16; o; o >>= 1) var += __shfl_xor_sync(0xffffffffu, var, o);
    float r = rsqrtf(var * (1.f / 64.f) + EPS);
    float yq0 = a0 * r * q_scale[lane], yq1 = a1 * r * q_scale[lane + 32];

    // ---- k LN ----
    mu = k0 + k1;
    #pragma unroll
    for (int o = 16; o; o >>= 1) mu += __shfl_xor_sync(0xffffffffu, mu, o);
    mu *= (1.f / 64.f);
    a0 = k0 - mu; a1 = k1 - mu;
    var = a0 * a0 + a1 * a1;
    #pragma unroll
    for (int o = 16; o; o >>= 1) var += __shfl_xor_sync(0xffffffffu, var, o);
    r = rsqrtf(var * (1.f / 64.f) + EPS);
    float yk0 = a0 * r * k_scale[lane], yk1 = a1 * r * k_scale[lane + 32];

    // ---- RoPE ----
    const float invf = (float)exp(-(double)(2 * lane) / 64.0 * log(10000.0));
    const float ang = (float)s * invf;
    const float c = cosf(ang), sn = sinf(ang);

    float oq0 = yq0 * c - yq1 * sn;
    float oq1 = yq1 * c + yq0 * sn;
    float ok0 = yk0 * c - yk1 * sn;
    float ok1 = yk1 * c + yk0 * sn;

    const size_t base = ((size_t)(b * HH + h) * SS + s) * HD;
    Q[base + lane] = oq0; Q[base + lane + 32] = oq1;
    K[base + lane] = ok0; K[base + lane + 32] = ok1;
    V[base + lane] = v0;  V[base + lane + 32] = v1;
}

// ---------------- kernel 4: flash attention, v2 ----------------------------
// Block = 128 threads, covers 128 query rows. tid = 2*m + h:
//   m in [0,64): query pair index; h in {0,1}: owns dims [32h, 32h+32).
// Thread handles TWO queries (q0+m, q0+64+m), sharing every K/V smem load
// between them -> 8 FMA per LDS.128 (2x the old ratio; L1 was the binding
// pipe at 74%). Score halves are combined with shfl_xor(.,1).
// No online max: after per-head LN, ||q||=||k||=8, so scores in [-8,8];
// exp never overflows and softmax is shift-invariant -> single fused pass.
// k4 iteration order is rotated by h so the pair's two LDS addresses differ
// by 16 mod 128 bytes (no bank conflict).
__global__ __launch_bounds__(128, 3) void flash_kernel(
    const float* __restrict__ Q, const float* __restrict__ K,
    const float* __restrict__ V, float* __restrict__ O)
{
    __shared__ float Ks[64 * 64];   // Ks[j*64 + d]
    __shared__ float Vs[64 * 64];   // Vs[j*64 + d]

    const int tid = threadIdx.x;
    const int m = tid >> 1;
    const int h = tid & 1;
    const int bh = blockIdx.y;                 // 0..31
    const int q0 = blockIdx.x * 128;
    const int r0 = q0 + m;
    const int r1 = q0 + 64 + m;

    // load both query rows' halves into registers
    float qa[32], qb[32];
    {
        const float4* Qa = (const float4*)(Q + ((size_t)bh * SS + r0) * HD + h * 32);
        const float4* Qb = (const float4*)(Q + ((size_t)bh * SS + r1) * HD + h * 32);
        #pragma unroll
        for (int d4 = 0; d4 < 8; d4++) {
            float4 a = Qa[d4];
            qa[4*d4+0] = a.x; qa[4*d4+1] = a.y; qa[4*d4+2] = a.z; qa[4*d4+3] = a.w;
            float4 b = Qb[d4];
            qb[4*d4+0] = b.x; qb[4*d4+1] = b.y; qb[4*d4+2] = b.z; qb[4*d4+3] = b.w;
        }
    }

    float acca[32], accb[32];
    #pragma unroll
    for (int d = 0; d < 32; d++) { acca[d] = 0.f; accb[d] = 0.f; }
    float la = 0.f, lb = 0.f;

    const float4* Ks4 = (const float4*)Ks;
    const float4* Vs4 = (const float4*)Vs;

    for (int kt = 0; kt < SS / 64; kt++) {
        const float4* Kb4 = (const float4*)(K + ((size_t)bh * SS + kt * 64) * HD);
        const float4* Vb4 = (const float4*)(V + ((size_t)bh * SS + kt * 64) * HD);
        __syncthreads();
        for (int e = tid; e < 1024; e += 128) {
            ((float4*)Ks)[e] = Kb4[e];
            ((float4*)Vs)[e] = Vb4[e];
        }
        __syncthreads();

        #pragma unroll 2
        for (int j = 0; j < 64; j++) {
            // ---- scores (half-dot, then pair-combine) ----
            const float4* kr = Ks4 + j * 16 + h * 8;
            float s0 = 0.f, s1 = 0.f, s2 = 0.f, s3 = 0.f;
            float t0 = 0.f, t1 = 0.f, t2 = 0.f, t3 = 0.f;
            #pragma unroll
            for (int k4 = 0; k4 < 8; k4++) {
                const int kk = (k4 + h) & 7;           // bank-conflict-free pair
                const float4 kv = kr[kk];
                s0 += qa[4*kk+0] * kv.x;
                s1 += qa[4*kk+1] * kv.y;
                s2 += qa[4*kk+2] * kv.z;
                s3 += qa[4*kk+3] * kv.w;
                t0 += qb[4*kk+0] * kv.x;
                t1 += qb[4*kk+1] * kv.y;
                t2 += qb[4*kk+2] * kv.z;
                t3 += qb[4*kk+3] * kv.w;
            }
            float sa = (s0 + s1) + (s2 + s3);
            float sb = (t0 + t1) + (t2 + t3);
            sa += __shfl_xor_sync(0xffffffffu, sa, 1);
            sb += __shfl_xor_sync(0xffffffffu, sb, 1);

            const float pa = __expf(sa * 0.125f);      // scale 1/sqrt(64)
            const float pb = __expf(sb * 0.125f);
            la += pa; lb += pb;

            // ---- accumulate p * V (shared loads) ----
            const float4* vr = Vs4 + j * 16 + h * 8;
            #pragma unroll
            for (int d4 = 0; d4 < 8; d4++) {
                const int kk = (d4 + h) & 7;
                const float4 vv = vr[kk];
                acca[4*kk+0] += pa * vv.x;
                acca[4*kk+1] += pa * vv.y;
                acca[4*kk+2] += pa * vv.z;
                acca[4*kk+3] += pa * vv.w;
                accb[4*kk+0] += pb * vv.x;
                accb[4*kk+1] += pb * vv.y;
                accb[4*kk+2] += pb * vv.z;
                accb[4*kk+3] += pb * vv.w;
            }
        }
    }

    const int b = bh >> 4, hh = bh & 15;
    const float inva = 1.f / la, invb = 1.f / lb;
    float* Oa = O + ((size_t)(b * SS + r0)) * DD + hh * HD + h * 32;
    float* Ob = O + ((size_t)(b * SS + r1)) * DD + hh * HD + h * 32;
    #pragma unroll
    for (int d4 = 0; d4 < 8; d4++) {
        float4 oa, ob;
        oa.x = acca[4*d4+0] * inva; oa.y = acca[4*d4+1] * inva;
        oa.z = acca[4*d4+2] * inva; oa.w = acca[4*d4+3] * inva;
        ob.x = accb[4*d4+0] * invb; ob.y = accb[4*d4+1] * invb;
        ob.z = accb[4*d4+2] * invb; ob.w = accb[4*d4+3] * invb;
        *(float4*)(Oa + d4 * 4) = oa;
        *(float4*)(Ob + d4 * 4) = ob;
    }
}

// ---------------- launcher -------------------------------------------------
extern "C" void kernel_launch(void* const* d_in, const int* in_sizes, int n_in,
                              void* d_out, int out_size)
{
    const float* x        = (const float*)d_in[0];
    const float* w_qkv    = (const float*)d_in[1];
    const float* b_qkv    = (const float*)d_in[2];
    const float* w_out    = (const float*)d_in[3];
    const float* b_out    = (const float*)d_in[4];
    const float* ln_scale = (const float*)d_in[5];
    const float* ln_bias  = (const float*)d_in[6];
    const float* q_scale  = (const float*)d_in[7];
    const float* k_scale  = (const float*)d_in[8];
    float* out = (float*)d_out;

    float *xn, *qkv, *q, *k, *v, *attn;
    cudaGetSymbolAddress((void**)&xn,   g_xn);
    cudaGetSymbolAddress((void**)&qkv,  g_qkv);
    cudaGetSymbolAddress((void**)&q,    g_q);
    cudaGetSymbolAddress((void**)&k,    g_k);
    cudaGetSymbolAddress((void**)&v,    g_v);
    cudaGetSymbolAddress((void**)&attn, g_attn);

    // 1) input layernorm
    ln_kernel<<<ROWS, 256>>>(x, ln_scale, ln_bias, xn);

    // 2) QKV projection: [4096,1024] @ [1024,3072]
    sgemm_bias<<<dim3(3 * DD / 128, ROWS / 128), 256>>>(xn, w_qkv, b_qkv, qkv,
                                                        ROWS, 3 * DD, DD);

    // 3) head LN + RoPE + layout change
    qk_rope_kernel<<<(BB * SS * HH) / 4, 128>>>(qkv, q_scale, k_scale, q, k, v);

    // 4) attention (128-query tiles, 2 queries/thread)
    flash_kernel<<<dim3(SS / 128, BB * HH), 128>>>(q, k, v, attn);

    // 5) output projection: [4096,1024] @ [1024,1024]
    sgemm_bias<<<dim3(DD / 128, ROWS / 128), 256>>>(attn, w_out, b_out, out,
                                                    ROWS, DD, DD);
}

// round 7
// speedup vs baseline: 5.8966x; 5.8966x over previous
#include <cuda_runtime.h>
#include <math.h>

// Problem dims
#define BB 2
#define SS 2048
#define DD 1024
#define HH 16
#define HD 64
#define ROWS (BB*SS)          // 4096
#define EPS 1e-6f

typedef unsigned long long u64;

// ---------------- packed f32x2 helpers (sm_103a FFMA2 pipe) ----------------
__device__ __forceinline__ u64 fma2(u64 a, u64 b, u64 c) {
    u64 d;
    asm("fma.rn.f32x2 %0, %1, %2, %3;" : "=l"(d) : "l"(a), "l"(b), "l"(c));
    return d;
}
__device__ __forceinline__ u64 mul2(u64 a, u64 b) {
    u64 d;
    asm("mul.rn.f32x2 %0, %1, %2;" : "=l"(d) : "l"(a), "l"(b));
    return d;
}
__device__ __forceinline__ u64 pack2(float lo, float hi) {
    u64 d;
    asm("mov.b64 %0, {%1, %2};" : "=l"(d) : "f"(lo), "f"(hi));
    return d;
}
__device__ __forceinline__ float lo2(u64 a) { return __uint_as_float((unsigned)a); }
__device__ __forceinline__ float hi2(u64 a) { return __uint_as_float((unsigned)(a >> 32)); }

// ---------------- scratch (device globals; no allocation allowed) ----------
__device__ float g_xn  [ROWS * DD];
__device__ float g_qkv [ROWS * 3 * DD];
__device__ float g_q   [BB * HH * SS * HD];  // [b,h,s,d]
__device__ float g_k   [BB * HH * SS * HD];
__device__ float g_v   [BB * HH * SS * HD];
__device__ float g_attn[ROWS * DD];          // [b,s,h*64+d]

// ---------------- kernel 1: row LayerNorm over D=1024 ---------------------
__global__ __launch_bounds__(256) void ln_kernel(
    const float* __restrict__ x, const float* __restrict__ scale,
    const float* __restrict__ bias, float* __restrict__ y)
{
    __shared__ float sh[8];
    const int t = threadIdx.x;
    const size_t row = blockIdx.x;
    const float* xr = x + row * DD;

    float v0 = xr[t], v1 = xr[t + 256], v2 = xr[t + 512], v3 = xr[t + 768];

    float s = v0 + v1 + v2 + v3;
    #pragma unroll
    for (int o = 16; o; o >>= 1) s += __shfl_xor_sync(0xffffffffu, s, o);
    if ((t & 31) == 0) sh[t >> 5] = s;
    __syncthreads();
    float tot = 0.f;
    #pragma unroll
    for (int i = 0; i < 8; i++) tot += sh[i];
    const float mean = tot * (1.f / 1024.f);

    float a0 = v0 - mean, a1 = v1 - mean, a2 = v2 - mean, a3 = v3 - mean;
    float sq = a0*a0 + a1*a1 + a2*a2 + a3*a3;
    #pragma unroll
    for (int o = 16; o; o >>= 1) sq += __shfl_xor_sync(0xffffffffu, sq, o);
    __syncthreads();
    if ((t & 31) == 0) sh[t >> 5] = sq;
    __syncthreads();
    float tsq = 0.f;
    #pragma unroll
    for (int i = 0; i < 8; i++) tsq += sh[i];
    const float rstd = rsqrtf(tsq * (1.f / 1024.f) + EPS);

    float* yr = y + row * DD;
    yr[t      ] = a0 * rstd * scale[t      ] + bias[t      ];
    yr[t + 256] = a1 * rstd * scale[t + 256] + bias[t + 256];
    yr[t + 512] = a2 * rstd * scale[t + 512] + bias[t + 512];
    yr[t + 768] = a3 * rstd * scale[t + 768] + bias[t + 768];
}

// ---------------- kernel 2: SGEMM 128x128x8, packed-f32x2 inner loop ------
// acc packed over i-pairs: acc[i2][j] = (C[2*i2][j], C[2*i2+1][j]).
// A pairs load directly as ulonglong2 from smem (consecutive i); B scalars
// duplicated with one mov.b64 each, reused across 4 packed FMAs.
__global__ __launch_bounds__(256) void sgemm_bias(
    const float* __restrict__ A, const float* __restrict__ B,
    const float* __restrict__ bias, float* __restrict__ C,
    int M, int N, int K)
{
    __shared__ float As[8][128];
    __shared__ float Bs[8][128];

    const int tid = threadIdx.x;
    const int tx = tid & 15;      // N direction
    const int ty = tid >> 4;      // M direction
    const int rowBase = blockIdx.y * 128;
    const int colBase = blockIdx.x * 128;

    const int aRow = tid >> 1;
    const int aCol = (tid & 1) * 4;
    const int bRow = tid >> 5;
    const int bCol = (tid & 31) * 4;

    u64 acc[4][8];                // [i-pair][j]
    #pragma unroll
    for (int i = 0; i < 4; i++)
        #pragma unroll
        for (int j = 0; j < 8; j++) acc[i][j] = 0ull;

    for (int k0 = 0; k0 < K; k0 += 8) {
        float4 a = *(const float4*)(A + (size_t)(rowBase + aRow) * K + k0 + aCol);
        As[aCol + 0][aRow] = a.x;
        As[aCol + 1][aRow] = a.y;
        As[aCol + 2][aRow] = a.z;
        As[aCol + 3][aRow] = a.w;
        float4 b = *(const float4*)(B + (size_t)(k0 + bRow) * N + colBase + bCol);
        *(float4*)&Bs[bRow][bCol] = b;
        __syncthreads();

        #pragma unroll
        for (int k = 0; k < 8; k++) {
            const ulonglong2* ap = (const ulonglong2*)&As[k][ty * 8];
            const float2*     bp = (const float2*)&Bs[k][tx * 8];
            ulonglong2 a01 = ap[0];          // (A[i0],A[i1]) , (A[i2],A[i3])
            ulonglong2 a23 = ap[1];
            #pragma unroll
            for (int j2 = 0; j2 < 4; j2++) {
                float2 bb = bp[j2];
                u64 rb0 = pack2(bb.x, bb.x);
                u64 rb1 = pack2(bb.y, bb.y);
                acc[0][2*j2  ] = fma2(a01.x, rb0, acc[0][2*j2  ]);
                acc[1][2*j2  ] = fma2(a01.y, rb0, acc[1][2*j2  ]);
                acc[2][2*j2  ] = fma2(a23.x, rb0, acc[2][2*j2  ]);
                acc[3][2*j2  ] = fma2(a23.y, rb0, acc[3][2*j2  ]);
                acc[0][2*j2+1] = fma2(a01.x, rb1, acc[0][2*j2+1]);
                acc[1][2*j2+1] = fma2(a01.y, rb1, acc[1][2*j2+1]);
                acc[2][2*j2+1] = fma2(a23.x, rb1, acc[2][2*j2+1]);
                acc[3][2*j2+1] = fma2(a23.y, rb1, acc[3][2*j2+1]);
            }
        }
        __syncthreads();
    }

    const int colT = colBase + tx * 8;
    #pragma unroll
    for (int i2 = 0; i2 < 4; i2++) {
        const size_t r0 = rowBase + ty * 8 + 2 * i2;
        const size_t r1 = r0 + 1;
        float4 o0a, o0b, o1a, o1b;
        o0a.x = lo2(acc[i2][0]) + bias[colT+0]; o1a.x = hi2(acc[i2][0]) + bias[colT+0];
        o0a.y = lo2(acc[i2][1]) + bias[colT+1]; o1a.y = hi2(acc[i2][1]) + bias[colT+1];
        o0a.z = lo2(acc[i2][2]) + bias[colT+2]; o1a.z = hi2(acc[i2][2]) + bias[colT+2];
        o0a.w = lo2(acc[i2][3]) + bias[colT+3]; o1a.w = hi2(acc[i2][3]) + bias[colT+3];
        o0b.x = lo2(acc[i2][4]) + bias[colT+4]; o1b.x = hi2(acc[i2][4]) + bias[colT+4];
        o0b.y = lo2(acc[i2][5]) + bias[colT+5]; o1b.y = hi2(acc[i2][5]) + bias[colT+5];
        o0b.z = lo2(acc[i2][6]) + bias[colT+6]; o1b.z = hi2(acc[i2][6]) + bias[colT+6];
        o0b.w = lo2(acc[i2][7]) + bias[colT+7]; o1b.w = hi2(acc[i2][7]) + bias[colT+7];
        *(float4*)(C + r0 * N + colT)     = o0a;
        *(float4*)(C + r0 * N + colT + 4) = o0b;
        *(float4*)(C + r1 * N + colT)     = o1a;
        *(float4*)(C + r1 * N + colT + 4) = o1b;
    }
}

// ---------------- kernel 3: per-head LN (q,k) + RoPE + transpose ----------
__global__ __launch_bounds__(128) void qk_rope_kernel(
    const float* __restrict__ qkv,
    const float* __restrict__ q_scale, const float* __restrict__ k_scale,
    float* __restrict__ Q, float* __restrict__ K, float* __restrict__ V)
{
    const int w = blockIdx.x * 4 + (threadIdx.x >> 5);
    const int lane = threadIdx.x & 31;
    const int h = w % HH;
    const int s = (w / HH) % SS;
    const int b = w / (HH * SS);

    const float* row = qkv + (size_t)(b * SS + s) * (3 * DD) + h * HD;
    float q0 = row[lane],        q1 = row[lane + 32];
    float k0 = row[DD + lane],   k1 = row[DD + lane + 32];
    float v0 = row[2*DD + lane], v1 = row[2*DD + lane + 32];

    float mu = q0 + q1;
    #pragma unroll
    for (int o = 16; o; o >>= 1) mu += __shfl_xor_sync(0xffffffffu, mu, o);
    mu *= (1.f / 64.f);
    float a0 = q0 - mu, a1 = q1 - mu;
    float var = a0 * a0 + a1 * a1;
    #pragma unroll
    for (int o = 16; o; o >>= 1) var += __shfl_xor_sync(0xffffffffu, var, o);
    float r = rsqrtf(var * (1.f / 64.f) + EPS);
    float yq0 = a0 * r * q_scale[lane], yq1 = a1 * r * q_scale[lane + 32];

    mu = k0 + k1;
    #pragma unroll
    for (int o = 16; o; o >>= 1) mu += __shfl_xor_sync(0xffffffffu, mu, o);
    mu *= (1.f / 64.f);
    a0 = k0 - mu; a1 = k1 - mu;
    var = a0 * a0 + a1 * a1;
    #pragma unroll
    for (int o = 16; o; o >>= 1) var += __shfl_xor_sync(0xffffffffu, var, o);
    r = rsqrtf(var * (1.f / 64.f) + EPS);
    float yk0 = a0 * r * k_scale[lane], yk1 = a1 * r * k_scale[lane + 32];

    const float invf = (float)exp(-(double)(2 * lane) / 64.0 * log(10000.0));
    const float ang = (float)s * invf;
    const float c = cosf(ang), sn = sinf(ang);

    float oq0 = yq0 * c - yq1 * sn;
    float oq1 = yq1 * c + yq0 * sn;
    float ok0 = yk0 * c - yk1 * sn;
    float ok1 = yk1 * c + yk0 * sn;

    const size_t base = ((size_t)(b * HH + h) * SS + s) * HD;
    Q[base + lane] = oq0; Q[base + lane + 32] = oq1;
    K[base + lane] = ok0; K[base + lane + 32] = ok1;
    V[base + lane] = v0;  V[base + lane + 32] = v1;
}

// ---------------- kernel 4: flash attention v3 (packed f32x2) -------------
// Block = 128 threads. tid = 2*m + h: m in [0,64) query-pair index,
// h in {0,1} owns dims [32h, 32h+32). Thread handles queries q0+m and
// q0+64+m, sharing every K/V smem load -> 4 FFMA2 per LDS.128.
// Smem layout: key row = 72 floats (36 u64); half h at j*36 + h*18 u64.
// Halves are 144 B apart -> bank groups differ by 4 -> conflict-free pair.
// All register-array indices are COMPILE-TIME (R6 spill lesson).
// No online max: post-LN scores bounded in [-8,8] (proven in R6 run).
__global__ __launch_bounds__(128, 2) void flash_kernel(
    const float* __restrict__ Q, const float* __restrict__ K,
    const float* __restrict__ V, float* __restrict__ O)
{
    __shared__ ulonglong2 Ks2[64 * 9 * 2];   // 64 keys * 18 ull2 (16 data + 2 pad)
    __shared__ ulonglong2 Vs2[64 * 9 * 2];

    const int tid = threadIdx.x;
    const int m = tid >> 1;
    const int h = tid & 1;
    const int bh = blockIdx.y;                 // 0..31
    const int q0 = blockIdx.x * 128;
    const int rA = q0 + m;
    const int rB = q0 + 64 + m;

    // load both query rows' halves as packed d-pairs
    u64 qA[16], qB[16];
    {
        const ulonglong2* Qa = (const ulonglong2*)(Q + ((size_t)bh * SS + rA) * HD + h * 32);
        const ulonglong2* Qb = (const ulonglong2*)(Q + ((size_t)bh * SS + rB) * HD + h * 32);
        #pragma unroll
        for (int i = 0; i < 8; i++) {
            ulonglong2 ta = Qa[i]; qA[2*i] = ta.x; qA[2*i+1] = ta.y;
            ulonglong2 tb = Qb[i]; qB[2*i] = tb.x; qB[2*i+1] = tb.y;
        }
    }

    u64 accA[16], accB[16];
    #pragma unroll
    for (int i = 0; i < 16; i++) { accA[i] = 0ull; accB[i] = 0ull; }
    float la = 0.f, lb = 0.f;

    for (int kt = 0; kt < SS / 64; kt++) {
        const ulonglong2* Kg = (const ulonglong2*)(K + ((size_t)bh * SS + kt * 64) * HD);
        const ulonglong2* Vg = (const ulonglong2*)(V + ((size_t)bh * SS + kt * 64) * HD);
        __syncthreads();
        for (int e = tid; e < 1024; e += 128) {
            const int j  = e >> 4;
            const int qq = e & 15;
            const int di = j * 18 + (qq >> 3) * 9 + (qq & 7);
            Ks2[di] = Kg[e];
            Vs2[di] = Vg[e];
        }
        __syncthreads();

        const ulonglong2* Ksh = Ks2 + h * 9;
        const ulonglong2* Vsh = Vs2 + h * 9;

        #pragma unroll 2
        for (int j = 0; j < 64; j++) {
            // ---- half-dot products, packed over d-pairs ----
            const ulonglong2* kr = Ksh + j * 18;
            u64 sa0 = 0ull, sa1 = 0ull, sb0 = 0ull, sb1 = 0ull;
            #pragma unroll
            for (int k4 = 0; k4 < 8; k4++) {
                ulonglong2 kk = kr[k4];
                sa0 = fma2(qA[2*k4  ], kk.x, sa0);
                sa1 = fma2(qA[2*k4+1], kk.y, sa1);
                sb0 = fma2(qB[2*k4  ], kk.x, sb0);
                sb1 = fma2(qB[2*k4+1], kk.y, sb1);
            }
            float sa = (lo2(sa0) + hi2(sa0)) + (lo2(sa1) + hi2(sa1));
            float sb = (lo2(sb0) + hi2(sb0)) + (lo2(sb1) + hi2(sb1));
            sa += __shfl_xor_sync(0xffffffffu, sa, 1);
            sb += __shfl_xor_sync(0xffffffffu, sb, 1);

            const float pa = __expf(sa * 0.125f);
            const float pb = __expf(sb * 0.125f);
            la += pa; lb += pb;
            const u64 ppa = pack2(pa, pa);
            const u64 ppb = pack2(pb, pb);

            // ---- accumulate p * V, packed over d-pairs ----
            const ulonglong2* vr = Vsh + j * 18;
            #pragma unroll
            for (int d4 = 0; d4 < 8; d4++) {
                ulonglong2 vv = vr[d4];
                accA[2*d4  ] = fma2(ppa, vv.x, accA[2*d4  ]);
                accA[2*d4+1] = fma2(ppa, vv.y, accA[2*d4+1]);
                accB[2*d4  ] = fma2(ppb, vv.x, accB[2*d4  ]);
                accB[2*d4+1] = fma2(ppb, vv.y, accB[2*d4+1]);
            }
        }
    }

    const int b = bh >> 4, hh = bh & 15;
    const u64 pia = pack2(1.f / la, 1.f / la);
    const u64 pib = pack2(1.f / lb, 1.f / lb);
    ulonglong2* Oa = (ulonglong2*)(O + ((size_t)(b * SS + rA)) * DD + hh * HD + h * 32);
    ulonglong2* Ob = (ulonglong2*)(O + ((size_t)(b * SS + rB)) * DD + hh * HD + h * 32);
    #pragma unroll
    for (int i = 0; i < 8; i++) {
        ulonglong2 ta, tb;
        ta.x = mul2(accA[2*i], pia); ta.y = mul2(accA[2*i+1], pia);
        tb.x = mul2(accB[2*i], pib); tb.y = mul2(accB[2*i+1], pib);
        Oa[i] = ta;
        Ob[i] = tb;
    }
}

// ---------------- launcher -------------------------------------------------
extern "C" void kernel_launch(void* const* d_in, const int* in_sizes, int n_in,
                              void* d_out, int out_size)
{
    const float* x        = (const float*)d_in[0];
    const float* w_qkv    = (const float*)d_in[1];
    const float* b_qkv    = (const float*)d_in[2];
    const float* w_out    = (const float*)d_in[3];
    const float* b_out    = (const float*)d_in[4];
    const float* ln_scale = (const float*)d_in[5];
    const float* ln_bias  = (const float*)d_in[6];
    const float* q_scale  = (const float*)d_in[7];
    const float* k_scale  = (const float*)d_in[8];
    float* out = (float*)d_out;

    float *xn, *qkv, *q, *k, *v, *attn;
    cudaGetSymbolAddress((void**)&xn,   g_xn);
    cudaGetSymbolAddress((void**)&qkv,  g_qkv);
    cudaGetSymbolAddress((void**)&q,    g_q);
    cudaGetSymbolAddress((void**)&k,    g_k);
    cudaGetSymbolAddress((void**)&v,    g_v);
    cudaGetSymbolAddress((void**)&attn, g_attn);

    // 1) input layernorm
    ln_kernel<<<ROWS, 256>>>(x, ln_scale, ln_bias, xn);

    // 2) QKV projection: [4096,1024] @ [1024,3072]
    sgemm_bias<<<dim3(3 * DD / 128, ROWS / 128), 256>>>(xn, w_qkv, b_qkv, qkv,
                                                        ROWS, 3 * DD, DD);

    // 3) head LN + RoPE + layout change
    qk_rope_kernel<<<(BB * SS * HH) / 4, 128>>>(qkv, q_scale, k_scale, q, k, v);

    // 4) attention (128-query tiles, 2 queries/thread, packed f32x2)
    flash_kernel<<<dim3(SS / 128, BB * HH), 128>>>(q, k, v, attn);

    // 5) output projection: [4096,1024] @ [1024,1024]
    sgemm_bias<<<dim3(DD / 128, ROWS / 128), 256>>>(attn, w_out, b_out, out,
                                                    ROWS, DD, DD);
}